// round 1
// baseline (speedup 1.0000x reference)
#include <cuda_runtime.h>
#include <math.h>

#define SEQ 2048
#define ND  128
#define NH  24      // 3*H concatenated heads
#define NC  32      // qk channels
#define PI2 6.283185307179586f

// Scratch (static device arrays: allocation-free per harness rules)
__device__ float g_k[SEQ * NH * NC];            // 6.3 MB  [i][h][c]
__device__ float g_q[SEQ * NH * NC];            // 6.3 MB  [j][h][c]
__device__ float g_v[SEQ * NH * ND];            // 25 MB   [j][h][d]
__device__ float g_part[NH * SEQ * ND];         // 25 MB   per-head partial outputs

// ---------------- projections: k/q from nodes / pos-features / rot ----------------
__global__ __launch_bounds__(256) void proj_kq_kernel(
    const float* __restrict__ nodes, const float* __restrict__ pos,
    const float* __restrict__ rot,
    const float* __restrict__ w_nodes, const float* __restrict__ b_nodes,
    const float* __restrict__ w_pos,  const float* __restrict__ b_pos,
    const float* __restrict__ w_rot)
{
    __shared__ float sn[16][128];
    __shared__ float sp[16][6];
    __shared__ float sr[16][4];
    const int i0  = blockIdx.x * 16;
    const int tid = threadIdx.x;

    for (int f = tid; f < 16 * 128; f += 256)
        sn[f >> 7][f & 127] = nodes[(i0 + (f >> 7)) * 128 + (f & 127)];
    if (tid < 16) {
        int i = i0 + tid;
        float p0 = pos[i * 3 + 0], p1 = pos[i * 3 + 1], p2 = pos[i * 3 + 2];
        sp[tid][0] = cosf(PI2 * p0); sp[tid][1] = cosf(PI2 * p1); sp[tid][2] = cosf(PI2 * p2);
        sp[tid][3] = sinf(PI2 * p0); sp[tid][4] = sinf(PI2 * p1); sp[tid][5] = sinf(PI2 * p2);
        sr[tid][0] = rot[i * 4 + 0]; sr[tid][1] = rot[i * 4 + 1];
        sr[tid][2] = rot[i * 4 + 2]; sr[tid][3] = rot[i * 4 + 3];
    }
    __syncthreads();

    // nodes source -> heads 0..7
    for (int o = tid; o < 512; o += 256) {
        float acc[16];
        float b = b_nodes[o];
        #pragma unroll
        for (int r = 0; r < 16; r++) acc[r] = b;
        const float* w = w_nodes + o * 128;
        for (int kk = 0; kk < 128; kk++) {
            float wv = __ldg(w + kk);
            #pragma unroll
            for (int r = 0; r < 16; r++) acc[r] += wv * sn[r][kk];
        }
        int hh = (o >> 6), cidx = o & 63;
        float* dst = (cidx < 32) ? g_k : g_q;
        int cc = cidx & 31;
        #pragma unroll
        for (int r = 0; r < 16; r++) dst[(i0 + r) * (NH * NC) + hh * NC + cc] = acc[r];
    }
    // pos source -> heads 8..15
    for (int o = tid; o < 512; o += 256) {
        float acc[16];
        float b = b_pos[o];
        #pragma unroll
        for (int r = 0; r < 16; r++) acc[r] = b;
        const float* w = w_pos + o * 6;
        for (int kk = 0; kk < 6; kk++) {
            float wv = __ldg(w + kk);
            #pragma unroll
            for (int r = 0; r < 16; r++) acc[r] += wv * sp[r][kk];
        }
        int hh = (o >> 6) + 8, cidx = o & 63;
        float* dst = (cidx < 32) ? g_k : g_q;
        int cc = cidx & 31;
        #pragma unroll
        for (int r = 0; r < 16; r++) dst[(i0 + r) * (NH * NC) + hh * NC + cc] = acc[r];
    }
    // rot source -> heads 16..23 (no bias)
    for (int o = tid; o < 512; o += 256) {
        float acc[16];
        #pragma unroll
        for (int r = 0; r < 16; r++) acc[r] = 0.f;
        const float* w = w_rot + o * 4;
        for (int kk = 0; kk < 4; kk++) {
            float wv = __ldg(w + kk);
            #pragma unroll
            for (int r = 0; r < 16; r++) acc[r] += wv * sr[r][kk];
        }
        int hh = (o >> 6) + 16, cidx = o & 63;
        float* dst = (cidx < 32) ? g_k : g_q;
        int cc = cidx & 31;
        #pragma unroll
        for (int r = 0; r < 16; r++) dst[(i0 + r) * (NH * NC) + hh * NC + cc] = acc[r];
    }
}

// ---------------- values projection: [S,3072] = nodes @ w_values^T + b ----------------
__global__ __launch_bounds__(256) void proj_val_kernel(
    const float* __restrict__ nodes,
    const float* __restrict__ w_values, const float* __restrict__ b_values)
{
    __shared__ float sn[16][128];
    const int i0  = blockIdx.x * 16;
    const int tid = threadIdx.x;
    const int o   = blockIdx.y * 256 + tid;    // 0..3071

    for (int f = tid; f < 16 * 128; f += 256)
        sn[f >> 7][f & 127] = nodes[(i0 + (f >> 7)) * 128 + (f & 127)];
    __syncthreads();

    float acc[16];
    float b = b_values[o];
    #pragma unroll
    for (int r = 0; r < 16; r++) acc[r] = b;
    const float* w = w_values + o * 128;
    for (int kk = 0; kk < 128; kk++) {
        float wv = __ldg(w + kk);
        #pragma unroll
        for (int r = 0; r < 16; r++) acc[r] += wv * sn[r][kk];
    }
    #pragma unroll
    for (int r = 0; r < 16; r++) g_v[(i0 + r) * (NH * ND) + o] = acc[r];
}

// ---------------- fused attention: one head per blockIdx.y, 32 query rows per block ----
__global__ __launch_bounds__(256) void attn_kernel()
{
    const int tid = threadIdx.x;
    const int h   = blockIdx.y;
    const int i0  = blockIdx.x * 32;

    __shared__ float sk[32][33];    // k rows (i), padded
    __shared__ float sq[32][33];    // q chunk (j), padded
    __shared__ float sl[32][33];    // probs, padded
    __shared__ float sv[32][128];   // v chunk (bank-clean for d = lane + 16*d')

    const int il = tid >> 4;        // 0..15 -> rows il and il+16
    const int c  = tid & 15;        // 0..15 -> cols c and c+16
    const int ia = il, ib = il + 16;

    for (int f = tid; f < 32 * 32; f += 256) {
        int r = f >> 5, cc = f & 31;
        sk[r][cc] = g_k[(i0 + r) * (NH * NC) + h * NC + cc];
    }

    float m_a = -1e30f, m_b = -1e30f, s_a = 0.f, s_b = 0.f;
    float acc0[8], acc1[8];
    #pragma unroll
    for (int d = 0; d < 8; d++) { acc0[d] = 0.f; acc1[d] = 0.f; }

    const bool sq_head = (h >= 16);

    for (int j0 = 0; j0 < SEQ; j0 += 32) {
        __syncthreads();
        for (int f = tid; f < 32 * 32; f += 256) {
            int r = f >> 5, cc = f & 31;
            sq[r][cc] = g_q[(j0 + r) * (NH * NC) + h * NC + cc];
        }
        {
            const float4* gv4 = (const float4*)g_v;
            for (int f = tid; f < 32 * 32; f += 256) {
                int r = f >> 5, c4 = f & 31;
                ((float4*)sv[r])[c4] = gv4[((j0 + r) * (NH * ND) + h * ND) / 4 + c4];
            }
        }
        __syncthreads();

        // 2x2 logit micro-tile
        float l00 = 0.f, l01 = 0.f, l10 = 0.f, l11 = 0.f;
        #pragma unroll
        for (int cc = 0; cc < 32; cc++) {
            float ka = sk[ia][cc], kb = sk[ib][cc];
            float qa = sq[c][cc],  qb = sq[c + 16][cc];
            l00 += ka * qa; l01 += ka * qb;
            l10 += kb * qa; l11 += kb * qb;
        }
        if (sq_head) { l00 *= l00; l01 *= l01; l10 *= l10; l11 *= l11; }

        // per-row chunk max (16-lane half-warp reductions)
        float cma = fmaxf(l00, l01);
        float cmb = fmaxf(l10, l11);
        #pragma unroll
        for (int off = 8; off > 0; off >>= 1) {
            cma = fmaxf(cma, __shfl_xor_sync(0xffffffffu, cma, off));
            cmb = fmaxf(cmb, __shfl_xor_sync(0xffffffffu, cmb, off));
        }
        float nma = fmaxf(m_a, cma), nmb = fmaxf(m_b, cmb);
        float ca = __expf(m_a - nma), cb = __expf(m_b - nmb);
        m_a = nma; m_b = nmb;

        float p00 = __expf(l00 - nma), p01 = __expf(l01 - nma);
        float p10 = __expf(l10 - nmb), p11 = __expf(l11 - nmb);
        float csa = p00 + p01, csb = p10 + p11;
        #pragma unroll
        for (int off = 8; off > 0; off >>= 1) {
            csa += __shfl_xor_sync(0xffffffffu, csa, off);
            csb += __shfl_xor_sync(0xffffffffu, csb, off);
        }
        s_a = s_a * ca + csa;
        s_b = s_b * cb + csb;
        #pragma unroll
        for (int d = 0; d < 8; d++) { acc0[d] *= ca; acc1[d] *= cb; }

        sl[ia][c] = p00; sl[ia][c + 16] = p01;
        sl[ib][c] = p10; sl[ib][c + 16] = p11;
        __syncwarp();

        // PV accumulate: d = c + 16*d' (conflict-free / broadcast in sv)
        #pragma unroll 4
        for (int jj = 0; jj < 32; jj++) {
            float pa = sl[ia][jj];
            float pb = sl[ib][jj];
            #pragma unroll
            for (int d = 0; d < 8; d++) {
                float v = sv[jj][c + 16 * d];
                acc0[d] += pa * v;
                acc1[d] += pb * v;
            }
        }
    }

    float inva = 1.f / s_a, invb = 1.f / s_b;
    float* base = g_part + (size_t)h * SEQ * ND;
    #pragma unroll
    for (int d = 0; d < 8; d++) {
        base[(i0 + ia) * ND + (c + 16 * d)] = acc0[d] * inva;
        base[(i0 + ib) * ND + (c + 16 * d)] = acc1[d] * invb;
    }
}

// ---------------- sum per-head partials (deterministic, no atomics) ----------------
__global__ __launch_bounds__(256) void reduce_kernel(float* __restrict__ out)
{
    int idx = blockIdx.x * 256 + threadIdx.x;   // 0 .. SEQ*ND-1
    float s = 0.f;
    #pragma unroll
    for (int hh = 0; hh < NH; hh++)
        s += g_part[(size_t)hh * SEQ * ND + idx];
    out[idx] = s;
}

extern "C" void kernel_launch(void* const* d_in, const int* in_sizes, int n_in,
                              void* d_out, int out_size)
{
    const float* nodes      = (const float*)d_in[0];
    const float* pos        = (const float*)d_in[1];
    const float* rot        = (const float*)d_in[2];
    const float* w_nodes_kq = (const float*)d_in[3];
    const float* b_nodes_kq = (const float*)d_in[4];
    const float* w_pos_kq   = (const float*)d_in[5];
    const float* b_pos_kq   = (const float*)d_in[6];
    const float* w_rot_kq   = (const float*)d_in[7];
    const float* w_values   = (const float*)d_in[8];
    const float* b_values   = (const float*)d_in[9];
    float* out = (float*)d_out;

    proj_kq_kernel<<<SEQ / 16, 256>>>(nodes, pos, rot,
                                      w_nodes_kq, b_nodes_kq,
                                      w_pos_kq, b_pos_kq, w_rot_kq);
    dim3 gv(SEQ / 16, 3072 / 256);
    proj_val_kernel<<<gv, 256>>>(nodes, w_values, b_values);

    dim3 ga(SEQ / 32, NH);
    attn_kernel<<<ga, 256>>>();

    reduce_kernel<<<(SEQ * ND) / 256, 256>>>(out);
}

// round 2
// speedup vs baseline: 1.6253x; 1.6253x over previous
#include <cuda_runtime.h>
#include <math.h>

#define SEQ 2048
#define ND  128
#define NH  24      // 3*H concatenated heads
#define NC  32      // qk channels
#define PI2 6.283185307179586f

// Scratch (static device arrays: allocation-free per harness rules)
__device__ float g_k[SEQ * NH * NC];            // 6.3 MB  [i][h][c]
__device__ float g_q[SEQ * NH * NC];            // 6.3 MB  [j][h][c]
__device__ float g_v[SEQ * NH * ND];            // 25 MB   [j][h][d]
__device__ float g_part[NH * SEQ * ND];         // 25 MB   per-head partial outputs

// ---------------- projections: k/q from nodes / pos-features / rot ----------------
__global__ __launch_bounds__(256) void proj_kq_kernel(
    const float* __restrict__ nodes, const float* __restrict__ pos,
    const float* __restrict__ rot,
    const float* __restrict__ w_nodes, const float* __restrict__ b_nodes,
    const float* __restrict__ w_pos,  const float* __restrict__ b_pos,
    const float* __restrict__ w_rot)
{
    __shared__ float sn[16][128];
    __shared__ float sp[16][6];
    __shared__ float sr[16][4];
    const int i0  = blockIdx.x * 16;
    const int tid = threadIdx.x;

    for (int f = tid; f < 16 * 128; f += 256)
        sn[f >> 7][f & 127] = nodes[(i0 + (f >> 7)) * 128 + (f & 127)];
    if (tid < 16) {
        int i = i0 + tid;
        float p0 = pos[i * 3 + 0], p1 = pos[i * 3 + 1], p2 = pos[i * 3 + 2];
        sp[tid][0] = cosf(PI2 * p0); sp[tid][1] = cosf(PI2 * p1); sp[tid][2] = cosf(PI2 * p2);
        sp[tid][3] = sinf(PI2 * p0); sp[tid][4] = sinf(PI2 * p1); sp[tid][5] = sinf(PI2 * p2);
        sr[tid][0] = rot[i * 4 + 0]; sr[tid][1] = rot[i * 4 + 1];
        sr[tid][2] = rot[i * 4 + 2]; sr[tid][3] = rot[i * 4 + 3];
    }
    __syncthreads();

    // nodes source -> heads 0..7
    for (int o = tid; o < 512; o += 256) {
        float acc[16];
        float b = b_nodes[o];
        #pragma unroll
        for (int r = 0; r < 16; r++) acc[r] = b;
        const float* w = w_nodes + o * 128;
        for (int kk = 0; kk < 128; kk++) {
            float wv = __ldg(w + kk);
            #pragma unroll
            for (int r = 0; r < 16; r++) acc[r] += wv * sn[r][kk];
        }
        int hh = (o >> 6), cidx = o & 63;
        float* dst = (cidx < 32) ? g_k : g_q;
        int cc = cidx & 31;
        #pragma unroll
        for (int r = 0; r < 16; r++) dst[(i0 + r) * (NH * NC) + hh * NC + cc] = acc[r];
    }
    // pos source -> heads 8..15
    for (int o = tid; o < 512; o += 256) {
        float acc[16];
        float b = b_pos[o];
        #pragma unroll
        for (int r = 0; r < 16; r++) acc[r] = b;
        const float* w = w_pos + o * 6;
        for (int kk = 0; kk < 6; kk++) {
            float wv = __ldg(w + kk);
            #pragma unroll
            for (int r = 0; r < 16; r++) acc[r] += wv * sp[r][kk];
        }
        int hh = (o >> 6) + 8, cidx = o & 63;
        float* dst = (cidx < 32) ? g_k : g_q;
        int cc = cidx & 31;
        #pragma unroll
        for (int r = 0; r < 16; r++) dst[(i0 + r) * (NH * NC) + hh * NC + cc] = acc[r];
    }
    // rot source -> heads 16..23 (no bias)
    for (int o = tid; o < 512; o += 256) {
        float acc[16];
        #pragma unroll
        for (int r = 0; r < 16; r++) acc[r] = 0.f;
        const float* w = w_rot + o * 4;
        for (int kk = 0; kk < 4; kk++) {
            float wv = __ldg(w + kk);
            #pragma unroll
            for (int r = 0; r < 16; r++) acc[r] += wv * sr[r][kk];
        }
        int hh = (o >> 6) + 16, cidx = o & 63;
        float* dst = (cidx < 32) ? g_k : g_q;
        int cc = cidx & 31;
        #pragma unroll
        for (int r = 0; r < 16; r++) dst[(i0 + r) * (NH * NC) + hh * NC + cc] = acc[r];
    }
}

// ---------------- values projection: [S,3072] = nodes @ w_values^T + b ----------------
__global__ __launch_bounds__(256) void proj_val_kernel(
    const float* __restrict__ nodes,
    const float* __restrict__ w_values, const float* __restrict__ b_values)
{
    __shared__ float sn[16][128];
    const int i0  = blockIdx.x * 16;
    const int tid = threadIdx.x;
    const int o   = blockIdx.y * 256 + tid;    // 0..3071

    for (int f = tid; f < 16 * 128; f += 256)
        sn[f >> 7][f & 127] = nodes[(i0 + (f >> 7)) * 128 + (f & 127)];
    __syncthreads();

    float acc[16];
    float b = b_values[o];
    #pragma unroll
    for (int r = 0; r < 16; r++) acc[r] = b;
    const float* w = w_values + o * 128;
    for (int kk = 0; kk < 128; kk++) {
        float wv = __ldg(w + kk);
        #pragma unroll
        for (int r = 0; r < 16; r++) acc[r] += wv * sn[r][kk];
    }
    #pragma unroll
    for (int r = 0; r < 16; r++) g_v[(i0 + r) * (NH * ND) + o] = acc[r];
}

// ---------------- fused attention: one head per blockIdx.y, 32 query rows per block ----
__global__ __launch_bounds__(256) void attn_kernel()
{
    const int tid = threadIdx.x;
    const int h   = blockIdx.y;
    const int i0  = blockIdx.x * 32;

    __shared__ float sk[32][33];    // k rows (i), padded
    __shared__ float sq[32][33];    // q chunk (j), padded
    __shared__ float sl[32][33];    // probs, padded
    __shared__ float sv[32][128];   // v chunk (bank-clean for d = lane + 16*d')

    const int il = tid >> 4;        // 0..15 -> rows il and il+16
    const int c  = tid & 15;        // 0..15 -> cols c and c+16
    const int ia = il, ib = il + 16;

    for (int f = tid; f < 32 * 32; f += 256) {
        int r = f >> 5, cc = f & 31;
        sk[r][cc] = g_k[(i0 + r) * (NH * NC) + h * NC + cc];
    }

    float m_a = -1e30f, m_b = -1e30f, s_a = 0.f, s_b = 0.f;
    float acc0[8], acc1[8];
    #pragma unroll
    for (int d = 0; d < 8; d++) { acc0[d] = 0.f; acc1[d] = 0.f; }

    const bool sq_head = (h >= 16);

    for (int j0 = 0; j0 < SEQ; j0 += 32) {
        __syncthreads();
        for (int f = tid; f < 32 * 32; f += 256) {
            int r = f >> 5, cc = f & 31;
            sq[r][cc] = g_q[(j0 + r) * (NH * NC) + h * NC + cc];
        }
        {
            const float4* gv4 = (const float4*)g_v;
            for (int f = tid; f < 32 * 32; f += 256) {
                int r = f >> 5, c4 = f & 31;
                ((float4*)sv[r])[c4] = gv4[((j0 + r) * (NH * ND) + h * ND) / 4 + c4];
            }
        }
        __syncthreads();

        // 2x2 logit micro-tile
        float l00 = 0.f, l01 = 0.f, l10 = 0.f, l11 = 0.f;
        #pragma unroll
        for (int cc = 0; cc < 32; cc++) {
            float ka = sk[ia][cc], kb = sk[ib][cc];
            float qa = sq[c][cc],  qb = sq[c + 16][cc];
            l00 += ka * qa; l01 += ka * qb;
            l10 += kb * qa; l11 += kb * qb;
        }
        if (sq_head) { l00 *= l00; l01 *= l01; l10 *= l10; l11 *= l11; }

        // per-row chunk max (16-lane half-warp reductions)
        float cma = fmaxf(l00, l01);
        float cmb = fmaxf(l10, l11);
        #pragma unroll
        for (int off = 8; off > 0; off >>= 1) {
            cma = fmaxf(cma, __shfl_xor_sync(0xffffffffu, cma, off));
            cmb = fmaxf(cmb, __shfl_xor_sync(0xffffffffu, cmb, off));
        }
        float nma = fmaxf(m_a, cma), nmb = fmaxf(m_b, cmb);
        float ca = __expf(m_a - nma), cb = __expf(m_b - nmb);
        m_a = nma; m_b = nmb;

        float p00 = __expf(l00 - nma), p01 = __expf(l01 - nma);
        float p10 = __expf(l10 - nmb), p11 = __expf(l11 - nmb);
        float csa = p00 + p01, csb = p10 + p11;
        #pragma unroll
        for (int off = 8; off > 0; off >>= 1) {
            csa += __shfl_xor_sync(0xffffffffu, csa, off);
            csb += __shfl_xor_sync(0xffffffffu, csb, off);
        }
        s_a = s_a * ca + csa;
        s_b = s_b * cb + csb;
        #pragma unroll
        for (int d = 0; d < 8; d++) { acc0[d] *= ca; acc1[d] *= cb; }

        sl[ia][c] = p00; sl[ia][c + 16] = p01;
        sl[ib][c] = p10; sl[ib][c + 16] = p11;
        __syncwarp();

        // PV accumulate: d = c + 16*d' (conflict-free / broadcast in sv)
        #pragma unroll 4
        for (int jj = 0; jj < 32; jj++) {
            float pa = sl[ia][jj];
            float pb = sl[ib][jj];
            #pragma unroll
            for (int d = 0; d < 8; d++) {
                float v = sv[jj][c + 16 * d];
                acc0[d] += pa * v;
                acc1[d] += pb * v;
            }
        }
    }

    float inva = 1.f / s_a, invb = 1.f / s_b;
    float* base = g_part + (size_t)h * SEQ * ND;
    #pragma unroll
    for (int d = 0; d < 8; d++) {
        base[(i0 + ia) * ND + (c + 16 * d)] = acc0[d] * inva;
        base[(i0 + ib) * ND + (c + 16 * d)] = acc1[d] * invb;
    }
}

// ---------------- sum per-head partials (deterministic, no atomics) ----------------
__global__ __launch_bounds__(256) void reduce_kernel(float* __restrict__ out)
{
    int idx = blockIdx.x * 256 + threadIdx.x;   // 0 .. SEQ*ND-1
    float s = 0.f;
    #pragma unroll
    for (int hh = 0; hh < NH; hh++)
        s += g_part[(size_t)hh * SEQ * ND + idx];
    out[idx] = s;
}

extern "C" void kernel_launch(void* const* d_in, const int* in_sizes, int n_in,
                              void* d_out, int out_size)
{
    const float* nodes      = (const float*)d_in[0];
    const float* pos        = (const float*)d_in[1];
    const float* rot        = (const float*)d_in[2];
    const float* w_nodes_kq = (const float*)d_in[3];
    const float* b_nodes_kq = (const float*)d_in[4];
    const float* w_pos_kq   = (const float*)d_in[5];
    const float* b_pos_kq   = (const float*)d_in[6];
    const float* w_rot_kq   = (const float*)d_in[7];
    const float* w_values   = (const float*)d_in[8];
    const float* b_values   = (const float*)d_in[9];
    float* out = (float*)d_out;

    proj_kq_kernel<<<SEQ / 16, 256>>>(nodes, pos, rot,
                                      w_nodes_kq, b_nodes_kq,
                                      w_pos_kq, b_pos_kq, w_rot_kq);
    dim3 gv(SEQ / 16, 3072 / 256);
    proj_val_kernel<<<gv, 256>>>(nodes, w_values, b_values);

    dim3 ga(SEQ / 32, NH);
    attn_kernel<<<ga, 256>>>();

    reduce_kernel<<<(SEQ * ND) / 256, 256>>>(out);
}

// round 3
// speedup vs baseline: 2.7903x; 1.7168x over previous
#include <cuda_runtime.h>
#include <math.h>

#define SEQ 2048
#define ND  128
#define NH  24
#define NC  32
#define BI  64
#define BJ  32
#define PI2 6.283185307179586f

typedef unsigned long long u64;

#define FMA2(d,a,b,c) asm("fma.rn.f32x2 %0,%1,%2,%3;":"=l"(d):"l"(a),"l"(b),"l"(c))
#define MUL2(d,a,b)   asm("mul.rn.f32x2 %0,%1,%2;":"=l"(d):"l"(a),"l"(b))
#define PACK2(d,lo,hi) asm("mov.b64 %0,{%1,%2};":"=l"(d):"f"(lo),"f"(hi))
#define UNPK2(lo,hi,v) asm("mov.b64 {%0,%1},%2;":"=f"(lo),"=f"(hi):"l"(v))

__device__ float g_k[NH*NC*SEQ];    // [h][c][i]
__device__ float g_q[NH*NC*SEQ];    // [h][c][j]
__device__ float g_v[NH*SEQ*ND];    // [h][j][d]
__device__ float g_part[NH*SEQ*ND];

__global__ __launch_bounds__(256) void proj_kq_kernel(
    const float* __restrict__ nodes, const float* __restrict__ pos,
    const float* __restrict__ rot,
    const float* __restrict__ w_nodes, const float* __restrict__ b_nodes,
    const float* __restrict__ w_pos, const float* __restrict__ b_pos,
    const float* __restrict__ w_rot)
{
    __shared__ float sn[16][128], sp[16][6], sr[16][4];
    const int i0 = blockIdx.x * 16, tid = threadIdx.x;
    for (int f = tid; f < 16*128; f += 256)
        sn[f>>7][f&127] = nodes[(i0+(f>>7))*128 + (f&127)];
    if (tid < 16) {
        int i = i0 + tid;
        float p0 = pos[i*3], p1 = pos[i*3+1], p2 = pos[i*3+2];
        sp[tid][0]=cosf(PI2*p0); sp[tid][1]=cosf(PI2*p1); sp[tid][2]=cosf(PI2*p2);
        sp[tid][3]=sinf(PI2*p0); sp[tid][4]=sinf(PI2*p1); sp[tid][5]=sinf(PI2*p2);
        sr[tid][0]=rot[i*4]; sr[tid][1]=rot[i*4+1]; sr[tid][2]=rot[i*4+2]; sr[tid][3]=rot[i*4+3];
    }
    __syncthreads();

    for (int o = tid; o < 512; o += 256) {   // nodes -> heads 0..7
        float acc[16], b = b_nodes[o];
        #pragma unroll
        for (int r = 0; r < 16; r++) acc[r] = b;
        const float4* w4 = (const float4*)(w_nodes + o*128);
        for (int k4 = 0; k4 < 32; k4++) {
            float4 wv = __ldg(w4 + k4);
            #pragma unroll
            for (int r = 0; r < 16; r++)
                acc[r] += wv.x*sn[r][4*k4] + wv.y*sn[r][4*k4+1] + wv.z*sn[r][4*k4+2] + wv.w*sn[r][4*k4+3];
        }
        int hh = o>>6, cx = o&63;
        float* dst = ((cx<32)?g_k:g_q) + (hh*NC + (cx&31))*SEQ + i0;
        #pragma unroll
        for (int r4 = 0; r4 < 4; r4++)
            ((float4*)dst)[r4] = make_float4(acc[4*r4],acc[4*r4+1],acc[4*r4+2],acc[4*r4+3]);
    }
    for (int o = tid; o < 512; o += 256) {   // pos -> heads 8..15
        float acc[16], b = b_pos[o];
        #pragma unroll
        for (int r = 0; r < 16; r++) acc[r] = b;
        const float* w = w_pos + o*6;
        for (int kk = 0; kk < 6; kk++) {
            float wv = __ldg(w+kk);
            #pragma unroll
            for (int r = 0; r < 16; r++) acc[r] += wv * sp[r][kk];
        }
        int hh = (o>>6)+8, cx = o&63;
        float* dst = ((cx<32)?g_k:g_q) + (hh*NC + (cx&31))*SEQ + i0;
        #pragma unroll
        for (int r4 = 0; r4 < 4; r4++)
            ((float4*)dst)[r4] = make_float4(acc[4*r4],acc[4*r4+1],acc[4*r4+2],acc[4*r4+3]);
    }
    for (int o = tid; o < 512; o += 256) {   // rot -> heads 16..23 (no bias)
        float acc[16];
        #pragma unroll
        for (int r = 0; r < 16; r++) acc[r] = 0.f;
        const float* w = w_rot + o*4;
        for (int kk = 0; kk < 4; kk++) {
            float wv = __ldg(w+kk);
            #pragma unroll
            for (int r = 0; r < 16; r++) acc[r] += wv * sr[r][kk];
        }
        int hh = (o>>6)+16, cx = o&63;
        float* dst = ((cx<32)?g_k:g_q) + (hh*NC + (cx&31))*SEQ + i0;
        #pragma unroll
        for (int r4 = 0; r4 < 4; r4++)
            ((float4*)dst)[r4] = make_float4(acc[4*r4],acc[4*r4+1],acc[4*r4+2],acc[4*r4+3]);
    }
}

// tiled GEMM: [S,3072] = nodes @ w^T + b, into g_v [h][j][d]
__global__ __launch_bounds__(256) void proj_val_kernel(
    const float* __restrict__ nodes,
    const float* __restrict__ w_values, const float* __restrict__ b_values)
{
    __shared__ float sa[32][128];
    __shared__ float sw[256][17];
    const int i0 = blockIdx.x*32, o0 = blockIdx.y*256, tid = threadIdx.x;
    const int g_i = tid>>5, g_o = tid&31;

    for (int f = tid; f < 32*128; f += 256)
        sa[f>>7][f&127] = nodes[(i0+(f>>7))*128 + (f&127)];

    float acc[4][8];
    #pragma unroll
    for (int e = 0; e < 8; e++) {
        float b = b_values[o0 + g_o + 32*e];
        #pragma unroll
        for (int r = 0; r < 4; r++) acc[r][e] = b;
    }
    for (int ks = 0; ks < 8; ks++) {
        __syncthreads();
        for (int f = tid; f < 256*16; f += 256)
            sw[f>>4][f&15] = w_values[(o0+(f>>4))*128 + ks*16 + (f&15)];
        __syncthreads();
        #pragma unroll 4
        for (int c = 0; c < 16; c++) {
            float a[4];
            #pragma unroll
            for (int r = 0; r < 4; r++) a[r] = sa[4*g_i+r][ks*16+c];
            #pragma unroll
            for (int e = 0; e < 8; e++) {
                float wv = sw[g_o+32*e][c];
                #pragma unroll
                for (int r = 0; r < 4; r++) acc[r][e] += a[r]*wv;
            }
        }
    }
    #pragma unroll
    for (int e = 0; e < 8; e++) {
        int o = o0 + g_o + 32*e, h = o>>7, dd = o&127;
        #pragma unroll
        for (int r = 0; r < 4; r++)
            g_v[((size_t)h*SEQ + i0+4*g_i+r)*ND + dd] = acc[r][e];
    }
}

// attention: BI=64 i-rows x 1 head per block, FFMA2 row-pairs
__global__ __launch_bounds__(256) void attn_kernel()
{
    const int tid = threadIdx.x, h = blockIdx.y, i0 = blockIdx.x*BI;
    const int t_hi = tid>>4, t_lo = tid&15, krow = 4*t_hi;

    __shared__ __align__(8) float skT[NC][BI];     // [c][i]
    __shared__ __align__(8) float sqT[NC][BJ];     // [c][j]
    __shared__ __align__(8) float slT[BJ][BI+2];   // [j][i]
    __shared__ __align__(8) float sv[BJ][ND];      // [j][d]

    const float* gk = g_k + h*NC*SEQ + i0;
    for (int f = tid; f < NC*BI; f += 256)
        skT[f>>6][f&63] = gk[(f>>6)*SEQ + (f&63)];

    float m[4], s[4];
    u64 acc[2][8];
    #pragma unroll
    for (int r = 0; r < 4; r++) { m[r] = -1e30f; s[r] = 0.f; }
    #pragma unroll
    for (int ri = 0; ri < 2; ri++)
        #pragma unroll
        for (int e = 0; e < 8; e++) acc[ri][e] = 0ull;

    const float* gq = g_q + h*NC*SEQ;
    const float* gv = g_v + (size_t)h*SEQ*ND;
    const bool sqh = (h >= 16);

    for (int j0 = 0; j0 < SEQ; j0 += BJ) {
        __syncthreads();
        for (int f = tid; f < NC*BJ; f += 256)
            sqT[f>>5][f&31] = gq[(f>>5)*SEQ + j0 + (f&31)];
        for (int f = tid; f < BJ*ND/4; f += 256)
            ((float4*)sv[f>>5])[f&31] = ((const float4*)gv)[(size_t)(j0+(f>>5))*(ND/4) + (f&31)];
        __syncthreads();

        u64 l2[2][2];
        #pragma unroll
        for (int ri = 0; ri < 2; ri++) { l2[ri][0] = 0ull; l2[ri][1] = 0ull; }
        #pragma unroll 8
        for (int cc = 0; cc < NC; cc++) {
            float2 q = *(const float2*)&sqT[cc][2*t_lo];
            u64 q0, q1; PACK2(q0, q.x, q.x); PACK2(q1, q.y, q.y);
            #pragma unroll
            for (int ri = 0; ri < 2; ri++) {
                u64 k2 = *(const u64*)&skT[cc][krow + 2*ri];
                FMA2(l2[ri][0], k2, q0, l2[ri][0]);
                FMA2(l2[ri][1], k2, q1, l2[ri][1]);
            }
        }
        float lg[4][2];
        #pragma unroll
        for (int ri = 0; ri < 2; ri++) {
            UNPK2(lg[2*ri][0], lg[2*ri+1][0], l2[ri][0]);
            UNPK2(lg[2*ri][1], lg[2*ri+1][1], l2[ri][1]);
        }
        if (sqh)
            #pragma unroll
            for (int r = 0; r < 4; r++) { lg[r][0] *= lg[r][0]; lg[r][1] *= lg[r][1]; }

        float ca[4];
        #pragma unroll
        for (int r = 0; r < 4; r++) {
            float cm = fmaxf(lg[r][0], lg[r][1]);
            #pragma unroll
            for (int off = 8; off > 0; off >>= 1)
                cm = fmaxf(cm, __shfl_xor_sync(0xffffffffu, cm, off));
            float nm = fmaxf(m[r], cm);
            ca[r] = __expf(m[r] - nm); m[r] = nm;
            float p0 = __expf(lg[r][0] - nm), p1 = __expf(lg[r][1] - nm);
            float cs = p0 + p1;
            #pragma unroll
            for (int off = 8; off > 0; off >>= 1)
                cs += __shfl_xor_sync(0xffffffffu, cs, off);
            s[r] = s[r]*ca[r] + cs;
            slT[2*t_lo][krow+r] = p0;
            slT[2*t_lo+1][krow+r] = p1;
        }
        #pragma unroll
        for (int ri = 0; ri < 2; ri++) {
            u64 c2; PACK2(c2, ca[2*ri], ca[2*ri+1]);
            #pragma unroll
            for (int e = 0; e < 8; e++) MUL2(acc[ri][e], acc[ri][e], c2);
        }
        __syncwarp();

        #pragma unroll 4
        for (int jj = 0; jj < BJ; jj++) {
            u64 vd[8];
            #pragma unroll
            for (int mm = 0; mm < 4; mm++) {
                float2 vf = *(const float2*)&sv[jj][32*mm + 2*t_lo];
                PACK2(vd[2*mm], vf.x, vf.x);
                PACK2(vd[2*mm+1], vf.y, vf.y);
            }
            #pragma unroll
            for (int ri = 0; ri < 2; ri++) {
                u64 p2 = *(const u64*)&slT[jj][krow + 2*ri];
                #pragma unroll
                for (int e = 0; e < 8; e++) FMA2(acc[ri][e], p2, vd[e], acc[ri][e]);
            }
        }
        __syncwarp();
    }

    float inv[4];
    #pragma unroll
    for (int r = 0; r < 4; r++) inv[r] = 1.f / s[r];
    float* gp = g_part + (size_t)h*SEQ*ND;
    #pragma unroll
    for (int ri = 0; ri < 2; ri++) {
        #pragma unroll
        for (int e = 0; e < 8; e++) {
            float x, y; UNPK2(x, y, acc[ri][e]);
            int d = 32*(e>>1) + 2*t_lo + (e&1);
            gp[(size_t)(i0+krow+2*ri)*ND + d]   = x * inv[2*ri];
            gp[(size_t)(i0+krow+2*ri+1)*ND + d] = y * inv[2*ri+1];
        }
    }
}

__global__ __launch_bounds__(256) void reduce_kernel(float* __restrict__ out)
{
    int idx = blockIdx.x*256 + threadIdx.x;
    float s = 0.f;
    #pragma unroll
    for (int hh = 0; hh < NH; hh++) s += g_part[(size_t)hh*SEQ*ND + idx];
    out[idx] = s;
}

extern "C" void kernel_launch(void* const* d_in, const int* in_sizes, int n_in,
                              void* d_out, int out_size)
{
    const float* nodes = (const float*)d_in[0];
    const float* pos   = (const float*)d_in[1];
    const float* rot   = (const float*)d_in[2];

    proj_kq_kernel<<<SEQ/16, 256>>>(nodes, pos, rot,
        (const float*)d_in[3], (const float*)d_in[4],
        (const float*)d_in[5], (const float*)d_in[6], (const float*)d_in[7]);
    dim3 gv(SEQ/32, 3072/256);
    proj_val_kernel<<<gv, 256>>>(nodes, (const float*)d_in[8], (const float*)d_in[9]);
    dim3 ga(SEQ/BI, NH);
    attn_kernel<<<ga, 256>>>();
    reduce_kernel<<<(SEQ*ND)/256, 256>>>((float*)d_out);
}